// round 11
// baseline (speedup 1.0000x reference)
#include <cuda_runtime.h>
#include <cstdint>

// tf32 mma.sync implicit-GEMM 3x3 valid conv.
// R11: B (input patch rows) persisted in smem once per CTA; only A (weights)
// streamed per K-chunk via 3-stage cp.async. Fused pre-pass.
//   x: (64,224,224) f32, w: (128,64,3,3) f32 -> out: (128,222,222) f32
// Layouts from pre-pass: xt[y][col(228)][ci64] tf32, wt[tap][co][ci] tf32.
// Tiles: M=64 (co half) x N=112. grid(2,222,2)=888 = 148*2 CTAs * 3 exact waves.

#define HW_IN  224
#define HW_OUT 222
#define C_IN   64
#define C_OUT  128
#define XT_W   228
#define NCH    18
#define OUT_HW (HW_OUT * HW_OUT)

#define SWZ(o) ((o) ^ (((o) >> 3) & 0x70))

#define A_STG    8192u
#define SM_B     (3u * A_STG)               // B region base (24576)
#define B_PLANE  43776u                     // 342 rows * 128 B
#define SM_MAIN  (SM_B + 2u * B_PLANE)      // 112,128 B

__device__ float wt_g[9 * 128 * 64];
__device__ float xt_g[224 * XT_W * 64];     // pad cols 224..227 stay zero (BSS)

__device__ __forceinline__ uint32_t smem_u32(const void* p) {
    uint32_t a;
    asm("{ .reg .u64 t; cvta.to.shared.u64 t, %1; cvt.u32.u64 %0, t; }" : "=r"(a) : "l"(p));
    return a;
}
__device__ __forceinline__ float f2tf32(float v) {
    uint32_t r; asm("cvt.rna.tf32.f32 %0, %1;" : "=r"(r) : "f"(v));
    return __uint_as_float(r);
}
__device__ __forceinline__ void cp16(uint32_t dst, const float* src) {
    asm volatile("cp.async.cg.shared.global [%0], [%1], 16;" :: "r"(dst), "l"(src) : "memory");
}
#define CP_COMMIT() asm volatile("cp.async.commit_group;" ::: "memory")
#define CP_WAIT1()  asm volatile("cp.async.wait_group 1;" ::: "memory")

__device__ __forceinline__ void ldsm4(uint32_t* d, uint32_t a) {
    asm volatile("ldmatrix.sync.aligned.m8n8.x4.shared.b16 {%0,%1,%2,%3}, [%4];"
                 : "=r"(d[0]), "=r"(d[1]), "=r"(d[2]), "=r"(d[3]) : "r"(a));
}
__device__ __forceinline__ void ldsm2(uint32_t* d, uint32_t a) {
    asm volatile("ldmatrix.sync.aligned.m8n8.x2.shared.b16 {%0,%1}, [%2];"
                 : "=r"(d[0]), "=r"(d[1]) : "r"(a));
}
__device__ __forceinline__ void mma8(float* c, const uint32_t* a, uint32_t b0, uint32_t b1) {
    asm volatile("mma.sync.aligned.m16n8k8.row.col.f32.tf32.tf32.f32 "
                 "{%0,%1,%2,%3}, {%4,%5,%6,%7}, {%8,%9}, {%0,%1,%2,%3};"
                 : "+f"(c[0]), "+f"(c[1]), "+f"(c[2]), "+f"(c[3])
                 : "r"(a[0]), "r"(a[1]), "r"(a[2]), "r"(a[3]), "r"(b0), "r"(b1));
}

// ---- fused pre-pass: blocks 0..223 transpose x row y; 224..511 convert w ----
__global__ void prep(const float* __restrict__ x, const float* __restrict__ w) {
    const int tid = threadIdx.x;
    if (blockIdx.x < 224) {
        extern __shared__ float s[];            // [64][225]
        const int y = blockIdx.x;
#pragma unroll 4
        for (int ci = 0; ci < 64; ci++)
            if (tid < 224)
                s[ci * 225 + tid] = f2tf32(x[ci * (HW_IN * HW_IN) + y * HW_IN + tid]);
        __syncthreads();
        for (int i = tid; i < 224 * 16; i += 256) {
            int col = i >> 4, q = i & 15;
            float4 v = make_float4(s[(4 * q + 0) * 225 + col], s[(4 * q + 1) * 225 + col],
                                   s[(4 * q + 2) * 225 + col], s[(4 * q + 3) * 225 + col]);
            *(float4*)&xt_g[((size_t)y * XT_W + col) * 64 + 4 * q] = v;
        }
    } else {
        int i = (blockIdx.x - 224) * 256 + tid;
        if (i < 9 * 128 * 64) {
            int ci = i & 63, co = (i >> 6) & 127, tap = i >> 13;
            wt_g[i] = f2tf32(w[co * 576 + ci * 9 + tap]);
        }
    }
}

// ---- main ----
__global__ __launch_bounds__(256, 2)
void conv_main(float* __restrict__ out)
{
    extern __shared__ char smem[];
    const uint32_t sb = smem_u32(smem);
    const uint32_t bbabs = sb + SM_B;
    const int tid = threadIdx.x, wid = tid >> 5, lane = tid & 31;
    const int bx = blockIdx.x, oy = blockIdx.y;
    const int n0 = bx * 112;
    const int co_base = blockIdx.z * 64;

    // A staging slots (2 cp16/thread, constant across chunks)
    uint32_t a_dst[2];
    int a_src[2];
#pragma unroll
    for (int t = 0; t < 2; t++) {
        int i = tid + t * 256, co = i >> 3, seg = i & 7;
        a_dst[t] = SWZ((uint32_t)(co * 128 + seg * 16));
        a_src[t] = co * 64 + seg * 4;
    }

    // mma addressing (R9/R10-validated mapping); B rows get +base(r,s,plane) later
    const int mi = lane >> 3, ri = lane & 7;
    const int m_loc = (wid & 3) * 16;
    const int n_loc = (wid >> 2) * 56;
    const uint32_t a_off = (uint32_t)(m_loc + (mi & 1) * 8 + ri) * 128u
                         + (uint32_t)(mi >> 1) * 16u;
    uint32_t b_off4[3];
#pragma unroll
    for (int p = 0; p < 3; p++)
        b_off4[p] = (uint32_t)(n_loc + p * 16 + (mi >> 1) * 8 + ri) * 128u
                  + (uint32_t)(mi & 1) * 16u;
    const uint32_t b_off2 = (uint32_t)(n_loc + 48 + (lane & 7)) * 128u
                          + (uint32_t)((lane >> 3) & 1) * 16u;

    float acc[7][4];
#pragma unroll
    for (int j = 0; j < 7; j++)
#pragma unroll
        for (int q = 0; q < 4; q++) acc[j][q] = 0.0f;

    const float* wbase = wt_g + co_base * 64;

#define ISSUE_A(c) do {                                                        \
        int _tap = (c) >> 1, _p = (c) & 1;                                     \
        const float* _as = wbase + _tap * 8192 + _p * 32;                      \
        uint32_t _stb = sb + (uint32_t)((c) % 3) * A_STG;                      \
        cp16(_stb + a_dst[0], _as + a_src[0]);                                 \
        cp16(_stb + a_dst[1], _as + a_src[1]);                                 \
    } while (0)

    // ---- prologue: B (full 2-plane patch) + A0 as group 0; A1 as group 1 ----
    {
        const float* xb = xt_g + ((size_t)oy * XT_W + n0) * 64;
        for (int i = tid; i < 5472; i += 256) {
            int p = i / 2736, rr = i - p * 2736;
            int row = rr >> 3, seg = rr & 7;        // row = r*114 + col
            int r = row / 114, col = row - r * 114;
            const float* src = xb + ((size_t)r * XT_W + col) * 64 + p * 32 + seg * 4;
            uint32_t off = (uint32_t)p * B_PLANE + ((uint32_t)row << 7) + (uint32_t)(seg * 16);
            cp16(bbabs + SWZ(off), src);
        }
        ISSUE_A(0);
        CP_COMMIT();          // G0 = {B, A0}
        ISSUE_A(1);
        CP_COMMIT();          // G1 = {A1}
    }

    int stg = 0;
#pragma unroll 1
    for (int c = 0; c < NCH; c++) {
        CP_WAIT1();           // chunk c's A (and B for c=0) landed
        __syncthreads();      // stage (c+2)%3 free for overwrite
        if (c + 2 < NCH) { ISSUE_A(c + 2); }
        CP_COMMIT();          // uniform group count

        const uint32_t ab = sb + (uint32_t)stg * A_STG;
        const int tap = c >> 1, p = c & 1;
        const int r = tap / 3, s = tap - 3 * r;
        const uint32_t bbase = (uint32_t)p * B_PLANE + (uint32_t)(r * 114 + s) * 128u;

#pragma unroll
        for (int ks = 0; ks < 4; ks++) {
            const uint32_t kb = (uint32_t)ks * 32u;
            uint32_t af[4], bfr[14];
            ldsm4(af, ab + SWZ(a_off + kb));
            ldsm4(&bfr[0],  bbabs + SWZ(bbase + b_off4[0] + kb));
            ldsm4(&bfr[4],  bbabs + SWZ(bbase + b_off4[1] + kb));
            ldsm4(&bfr[8],  bbabs + SWZ(bbase + b_off4[2] + kb));
            ldsm2(&bfr[12], bbabs + SWZ(bbase + b_off2 + kb));
#pragma unroll
            for (int j = 0; j < 7; j++)
                mma8(acc[j], af, bfr[2 * j], bfr[2 * j + 1]);
        }
        stg++; if (stg == 3) stg = 0;
    }
#undef ISSUE_A

    // ---- epilogue: direct float2 STG ----
    const int gid = lane >> 2, tig = lane & 3;
    const int co0 = co_base + m_loc + gid;
    const int co1 = co0 + 8;
#pragma unroll
    for (int j = 0; j < 7; j++) {
        int local = n_loc + j * 8 + tig * 2;
        if (bx == 0 || local < 110) {
            size_t ro = (size_t)oy * HW_OUT + n0 + local;
            *(float2*)&out[(size_t)co0 * OUT_HW + ro] = make_float2(acc[j][0], acc[j][1]);
            *(float2*)&out[(size_t)co1 * OUT_HW + ro] = make_float2(acc[j][2], acc[j][3]);
        }
    }
}

extern "C" void kernel_launch(void* const* d_in, const int* in_sizes, int n_in,
                              void* d_out, int out_size)
{
    const float* x = (const float*)d_in[0];
    const float* w = (const float*)d_in[1];
    if (n_in >= 2 && in_sizes[0] == C_OUT * C_IN * 9 &&
        in_sizes[1] == C_IN * HW_IN * HW_IN) {
        w = (const float*)d_in[0];
        x = (const float*)d_in[1];
    }
    float* out = (float*)d_out;

    cudaFuncSetAttribute(prep, cudaFuncAttributeMaxDynamicSharedMemorySize, 64 * 225 * 4);
    cudaFuncSetAttribute(conv_main, cudaFuncAttributeMaxDynamicSharedMemorySize, SM_MAIN);

    prep<<<512, 256, 64 * 225 * 4>>>(x, w);
    conv_main<<<dim3(2, HW_OUT, 2), 256, SM_MAIN>>>(out);
}